// round 16
// baseline (speedup 1.0000x reference)
#include <cuda_runtime.h>
#include <cstdint>
#include <cstddef>

#define N_     50000
#define E_     800000
#define EN_    100000
#define ET_    900000
#define NREL_  500

// ---------------- scratch (__device__ globals; no cudaMalloc allowed) ----------------
__device__ int   g_cnt[N_];
__device__ int   g_cur[N_];
__device__ int   g_start[N_ + 1];
__device__ int   g_csr[ET_];

__device__ float g_B1[256 * 128];          // layer-1 packed src|dst proj rows
__device__ float g_B2[256 * 128];          // layer-2 packed src|dst proj rows
__device__ float g_arel[2 * 64 * 128];     // per-head a_rel [h][j][k]
__device__ float g_u1[2 * 128];            // u_h = a_rel_h^T a2_h

__device__ float g_pm1[(size_t)N_ * 256];  // [n][src h0|src h1|dst h0|dst h1]
__device__ float g_s1[N_ * 4];             // [n][ssrc0 ssrc1 sdst0 sdst1]
__device__ float g_agg[(size_t)N_ * 256];  // [n][h0 v-agg 128 | h1 v-agg 128]
__device__ float g_aggdst[(size_t)N_ * 128];
__device__ float g_rs1[N_ * 2];
__device__ float g_hp[(size_t)N_ * 128];
__device__ float g_x2[(size_t)N_ * 128];
__device__ float g_pm2[(size_t)N_ * 256];  // [n][src 128 | dst 128]
__device__ float g_s2[N_ * 2];
__device__ float g_relproj2[NREL_ * 128];
__device__ float g_rels2[NREL_];

// ---------------- helpers ----------------
__device__ __forceinline__ float eluf(float x) { return x > 0.f ? x : expm1f(x); }
__device__ __forceinline__ float attw(float p) {
    float lk = p > 0.f ? p : 0.2f * p;     // leaky_relu(p, 0.2)
    return __expf(-lk);
}

// ---------------- small precompute ----------------
__global__ void k_prep(const float* __restrict__ ah, const float* __restrict__ ao,
                       const float* __restrict__ a2h) {
    int idx = blockIdx.x * blockDim.x + threadIdx.x;
    if (idx < 32768) {                       // B1
        int r = idx >> 7, k = idx & 127;
        int rr = (r < 128) ? r : r - 128;
        int h = rr >> 6, j = rr & 63;
        int kk = (r < 128) ? k : 128 + k;
        g_B1[idx] = ah[(h * 64 + j) * 384 + kk];
    } else if (idx < 65536) {                // B2
        int e = idx - 32768;
        int r = e >> 7, k = e & 127;
        g_B2[e] = (r < 128) ? ao[r * 384 + k] : ao[(r - 128) * 384 + 128 + k];
    } else if (idx < 81920) {                // arel
        int e = idx - 65536;
        int h = e >> 13, j = (e >> 7) & 63, k = e & 127;
        g_arel[e] = ah[(h * 64 + j) * 384 + 256 + k];
    } else if (idx < 82176) {                // u1
        int e = idx - 81920;
        int h = e >> 7, k = e & 127;
        float s = 0.f;
        for (int j = 0; j < 64; ++j)
            s = fmaf(ah[(h * 64 + j) * 384 + 256 + k], a2h[h * 64 + j], s);
        g_u1[e] = s;
    }
}

__global__ void k_outrel(const float* __restrict__ rel, const float* __restrict__ W,
                         float* __restrict__ out_rel) {
    int idx = blockIdx.x * blockDim.x + threadIdx.x;
    if (idx >= NREL_ * 128) return;
    int r = idx >> 7, c = idx & 127;
    float s = 0.f;
    #pragma unroll 8
    for (int k = 0; k < 128; ++k) s = fmaf(rel[r * 128 + k], W[k * 128 + c], s);
    out_rel[idx] = s;
}

__global__ void k_relproj2(const float* __restrict__ out_rel, const float* __restrict__ ao) {
    int idx = blockIdx.x * blockDim.x + threadIdx.x;
    if (idx >= NREL_ * 128) return;
    int r = idx >> 7, j = idx & 127;
    float s = 0.f;
    #pragma unroll 8
    for (int k = 0; k < 128; ++k) s = fmaf(out_rel[r * 128 + k], ao[j * 384 + 256 + k], s);
    g_relproj2[idx] = s;
}

__global__ void k_rels2(const float* __restrict__ a2o) {
    int r = blockIdx.x * blockDim.x + threadIdx.x;
    if (r >= NREL_) return;
    float s = 0.f;
    #pragma unroll 8
    for (int j = 0; j < 128; ++j) s = fmaf(g_relproj2[r * 128 + j], a2o[j], s);
    g_rels2[r] = s;
}

// ---------------- CSR build (shared by both layers; same e0) ----------------
__global__ void k_zero() {
    int i = blockIdx.x * blockDim.x + threadIdx.x;
    if (i < N_) { g_cnt[i] = 0; g_cur[i] = 0; }
}

__global__ void k_hist(const int* __restrict__ el, const int* __restrict__ elnh) {
    for (int i = blockIdx.x * blockDim.x + threadIdx.x; i < ET_; i += gridDim.x * blockDim.x) {
        int n = (i < E_) ? el[i] : elnh[i - E_];
        atomicAdd(&g_cnt[n], 1);
    }
}

__global__ void k_scan() {
    __shared__ int sm[1024];
    const int t = threadIdx.x;
    const int C = 49;                       // 1024*49 >= 50000
    int base = t * C;
    int s = 0;
    for (int i = 0; i < C; ++i) { int idx = base + i; if (idx < N_) s += g_cnt[idx]; }
    sm[t] = s;
    __syncthreads();
    for (int off = 1; off < 1024; off <<= 1) {
        int v = (t >= off) ? sm[t - off] : 0;
        __syncthreads();
        sm[t] += v;
        __syncthreads();
    }
    int run = sm[t] - s;                    // exclusive prefix
    for (int i = 0; i < C; ++i) {
        int idx = base + i;
        if (idx < N_) { g_start[idx] = run; run += g_cnt[idx]; }
    }
    if (t == 1023) g_start[N_] = sm[1023];
}

__global__ void k_scatter(const int* __restrict__ el, const int* __restrict__ elnh) {
    for (int i = blockIdx.x * blockDim.x + threadIdx.x; i < ET_; i += gridDim.x * blockDim.x) {
        int n = (i < E_) ? el[i] : elnh[i - E_];
        int pos = g_start[n] + atomicAdd(&g_cur[n], 1);
        g_csr[pos] = i;
    }
}

// ---------------- SGEMM: C[M,*] = A[M,128] @ B[*,128]^T, 128x64 tile ----------------
__device__ __forceinline__ void sgemm_body(int M, const float* __restrict__ A, int lda,
                                           const float* __restrict__ B,
                                           float* __restrict__ C, int ldc) {
    __shared__ float As[32][129];
    __shared__ float Bs[32][65];
    const int tid = threadIdx.x;
    const int rb = blockIdx.y * 128;
    const int nb = blockIdx.x * 64;
    const int m0 = (tid >> 3) * 8;
    const int n0 = (tid & 7) * 8;
    float acc[8][8] = {};
    for (int kc = 0; kc < 128; kc += 32) {
        #pragma unroll
        for (int it = 0; it < 8; ++it) {
            int fidx = tid + it * 128;
            int r = fidx >> 3, q = fidx & 7;
            float4 v = make_float4(0.f, 0.f, 0.f, 0.f);
            int row = rb + r;
            if (row < M) v = *reinterpret_cast<const float4*>(A + (size_t)row * lda + kc + q * 4);
            As[q * 4 + 0][r] = v.x; As[q * 4 + 1][r] = v.y;
            As[q * 4 + 2][r] = v.z; As[q * 4 + 3][r] = v.w;
        }
        #pragma unroll
        for (int it = 0; it < 4; ++it) {
            int fidx = tid + it * 128;
            int r = fidx >> 3, q = fidx & 7;
            float4 v = *reinterpret_cast<const float4*>(B + (size_t)(nb + r) * 128 + kc + q * 4);
            Bs[q * 4 + 0][r] = v.x; Bs[q * 4 + 1][r] = v.y;
            Bs[q * 4 + 2][r] = v.z; Bs[q * 4 + 3][r] = v.w;
        }
        __syncthreads();
        #pragma unroll
        for (int k = 0; k < 32; ++k) {
            float a[8], b[8];
            #pragma unroll
            for (int i = 0; i < 8; ++i) a[i] = As[k][m0 + i];
            #pragma unroll
            for (int j = 0; j < 8; ++j) b[j] = Bs[k][n0 + j];
            #pragma unroll
            for (int i = 0; i < 8; ++i)
                #pragma unroll
                for (int j = 0; j < 8; ++j)
                    acc[i][j] = fmaf(a[i], b[j], acc[i][j]);
        }
        __syncthreads();
    }
    #pragma unroll
    for (int i = 0; i < 8; ++i) {
        int row = rb + m0 + i;
        if (row < M) {
            *reinterpret_cast<float4*>(C + (size_t)row * ldc + nb + n0) =
                make_float4(acc[i][0], acc[i][1], acc[i][2], acc[i][3]);
            *reinterpret_cast<float4*>(C + (size_t)row * ldc + nb + n0 + 4) =
                make_float4(acc[i][4], acc[i][5], acc[i][6], acc[i][7]);
        }
    }
}

__global__ void __launch_bounds__(128) k_gemm_pm1(const float* __restrict__ A) {
    sgemm_body(N_, A, 128, g_B1, g_pm1, 256);
}
__global__ void __launch_bounds__(128) k_gemm_pm2() {
    sgemm_body(N_, g_x2, 128, g_B2, g_pm2, 256);
}
__global__ void __launch_bounds__(128) k_gemm_hp0() {
    sgemm_body(N_, g_agg, 256, g_arel, g_hp, 128);
}
__global__ void __launch_bounds__(128) k_gemm_hp1() {
    sgemm_body(N_, g_agg + 128, 256, g_arel + 64 * 128, g_hp + 64, 128);
}

// ---------------- per-node logit scalars ----------------
__global__ void k_s1(const float* __restrict__ a2h) {
    int w = (blockIdx.x * blockDim.x + threadIdx.x) >> 5;
    int l = threadIdx.x & 31;
    if (w >= N_) return;
    const float* row = g_pm1 + (size_t)w * 256;
    float ps[4] = {0.f, 0.f, 0.f, 0.f};
    #pragma unroll
    for (int i = 0; i < 8; ++i) {
        int idx = l + 32 * i;
        int s = i >> 1;                 // 0:src h0, 1:src h1, 2:dst h0, 3:dst h1
        int head = s & 1;
        ps[s] = fmaf(row[idx], a2h[head * 64 + (idx & 63)], ps[s]);
    }
    #pragma unroll
    for (int off = 16; off; off >>= 1) {
        #pragma unroll
        for (int s = 0; s < 4; ++s) ps[s] += __shfl_xor_sync(0xffffffffu, ps[s], off);
    }
    if (l == 0) {
        g_s1[w * 4 + 0] = ps[0]; g_s1[w * 4 + 1] = ps[1];
        g_s1[w * 4 + 2] = ps[2]; g_s1[w * 4 + 3] = ps[3];
    }
}

__global__ void k_s2(const float* __restrict__ a2o) {
    int w = (blockIdx.x * blockDim.x + threadIdx.x) >> 5;
    int l = threadIdx.x & 31;
    if (w >= N_) return;
    const float4* pm4 = (const float4*)g_pm2;
    const float4* a4 = (const float4*)a2o;
    float4 av = a4[l];
    float4 sv = pm4[(size_t)w * 64 + l];
    float4 dv = pm4[(size_t)w * 64 + 32 + l];
    float p0 = sv.x * av.x + sv.y * av.y + sv.z * av.z + sv.w * av.w;
    float p1 = dv.x * av.x + dv.y * av.y + dv.z * av.z + dv.w * av.w;
    #pragma unroll
    for (int off = 16; off; off >>= 1) {
        p0 += __shfl_xor_sync(0xffffffffu, p0, off);
        p1 += __shfl_xor_sync(0xffffffffu, p1, off);
    }
    if (l == 0) { g_s2[2 * w] = p0; g_s2[2 * w + 1] = p1; }
}

// ---------------- layer-1 edge pass (warp per node) ----------------
__global__ void k_edge1(const int* __restrict__ el, const int* __restrict__ elnh,
                        const int* __restrict__ etnh,
                        const float* __restrict__ eemb, const float* __restrict__ rel) {
    int w = (blockIdx.x * blockDim.x + threadIdx.x) >> 5;
    int l = threadIdx.x & 31;
    if (w >= N_) return;
    const float4* eemb4 = (const float4*)eemb;
    const float4* rel4 = (const float4*)rel;
    const float4* u4 = (const float4*)g_u1;
    const float4* pm4 = (const float4*)g_pm1;
    float4 u0 = u4[l], u1 = u4[32 + l];
    float ssrc0 = g_s1[w * 4 + 0], ssrc1 = g_s1[w * 4 + 1];
    float4 a0 = make_float4(0.f, 0.f, 0.f, 0.f);
    float4 a1 = make_float4(0.f, 0.f, 0.f, 0.f);
    float4 ad = make_float4(0.f, 0.f, 0.f, 0.f);
    float rs0 = 0.f, rs1 = 0.f;
    int s = g_start[w], e = g_start[w + 1];
    for (int p = s; p < e; ++p) {
        int eid = g_csr[p];
        int dst; float4 v;
        if (eid < E_) {
            dst = el[E_ + eid];
            v = eemb4[(size_t)eid * 32 + l];
        } else {
            int q = eid - E_;
            dst = elnh[EN_ + q];
            int t0 = etnh[2 * q], t1 = etnh[2 * q + 1];
            float4 x = rel4[t0 * 32 + l], y = rel4[t1 * 32 + l];
            v = make_float4(x.x + y.x, x.y + y.y, x.z + y.z, x.w + y.w);
        }
        float d0 = v.x * u0.x + v.y * u0.y + v.z * u0.z + v.w * u0.w;
        float d1 = v.x * u1.x + v.y * u1.y + v.z * u1.z + v.w * u1.w;
        #pragma unroll
        for (int off = 16; off; off >>= 1) {
            d0 += __shfl_xor_sync(0xffffffffu, d0, off);
            d1 += __shfl_xor_sync(0xffffffffu, d1, off);
        }
        float w0 = attw(ssrc0 + g_s1[dst * 4 + 2] + d0);
        float w1 = attw(ssrc1 + g_s1[dst * 4 + 3] + d1);
        rs0 += w0; rs1 += w1;
        a0.x = fmaf(w0, v.x, a0.x); a0.y = fmaf(w0, v.y, a0.y);
        a0.z = fmaf(w0, v.z, a0.z); a0.w = fmaf(w0, v.w, a0.w);
        a1.x = fmaf(w1, v.x, a1.x); a1.y = fmaf(w1, v.y, a1.y);
        a1.z = fmaf(w1, v.z, a1.z); a1.w = fmaf(w1, v.w, a1.w);
        float4 pd = pm4[(size_t)dst * 64 + 32 + l];   // dst-proj, both heads packed
        float ww = (l < 16) ? w0 : w1;
        ad.x = fmaf(ww, pd.x, ad.x); ad.y = fmaf(ww, pd.y, ad.y);
        ad.z = fmaf(ww, pd.z, ad.z); ad.w = fmaf(ww, pd.w, ad.w);
    }
    float4* agg4 = (float4*)g_agg;
    agg4[(size_t)w * 64 + l] = a0;
    agg4[(size_t)w * 64 + 32 + l] = a1;
    ((float4*)g_aggdst)[(size_t)w * 32 + l] = ad;
    if (l == 0) { g_rs1[2 * w] = rs0; g_rs1[2 * w + 1] = rs1; }
}

// ---------------- layer-1 finalize: x2 = elu(h) ----------------
__global__ void k_fin1() {
    int idx = blockIdx.x * blockDim.x + threadIdx.x;
    if (idx >= N_ * 128) return;
    int n = idx >> 7, j = idx & 127, h = j >> 6;
    float rs = g_rs1[2 * n + h];
    float num = fmaf(rs, g_pm1[(size_t)n * 256 + j],
                     g_aggdst[(size_t)n * 128 + j] + g_hp[(size_t)n * 128 + j]);
    float rsadj = (rs == 0.f) ? 1e-12f : rs;
    g_x2[(size_t)n * 128 + j] = eluf(num / rsadj);
}

// ---------------- layer-2 edge pass + fused finalize ----------------
__global__ void k_edge2(const int* __restrict__ el, const int* __restrict__ elnh,
                        const int* __restrict__ et, const int* __restrict__ etnh,
                        float* __restrict__ out0, float* __restrict__ out2,
                        float* __restrict__ out3) {
    int w = (blockIdx.x * blockDim.x + threadIdx.x) >> 5;
    int l = threadIdx.x & 31;
    if (w >= N_) return;
    const float4* pm4 = (const float4*)g_pm2;
    const float4* rp4 = (const float4*)g_relproj2;
    float4 ps = pm4[(size_t)w * 64 + l];
    float ssrc = g_s2[2 * w];
    float4 num = make_float4(0.f, 0.f, 0.f, 0.f);
    float4 unif = make_float4(0.f, 0.f, 0.f, 0.f);
    float rs = 0.f, cnt = 0.f;
    int s = g_start[w], e = g_start[w + 1];
    for (int p = s; p < e; ++p) {
        int eid = g_csr[p];
        int dst; float4 rp; float rels;
        if (eid < E_) {
            dst = el[E_ + eid];
            int r = et[eid];
            rp = rp4[r * 32 + l];
            rels = g_rels2[r];
        } else {
            int q = eid - E_;
            dst = elnh[EN_ + q];
            int t0 = etnh[2 * q], t1 = etnh[2 * q + 1];
            float4 x = rp4[t0 * 32 + l], y = rp4[t1 * 32 + l];
            rp = make_float4(x.x + y.x, x.y + y.y, x.z + y.z, x.w + y.w);
            rels = g_rels2[t0] + g_rels2[t1];
        }
        float4 pd = pm4[(size_t)dst * 64 + 32 + l];
        float wgt = attw(ssrc + g_s2[2 * dst + 1] + rels);
        float4 m = make_float4(ps.x + pd.x + rp.x, ps.y + pd.y + rp.y,
                               ps.z + pd.z + rp.z, ps.w + pd.w + rp.w);
        rs += wgt; cnt += 1.f;
        num.x = fmaf(wgt, m.x, num.x); num.y = fmaf(wgt, m.y, num.y);
        num.z = fmaf(wgt, m.z, num.z); num.w = fmaf(wgt, m.w, num.w);
        unif.x += m.x; unif.y += m.y; unif.z += m.z; unif.w += m.w;
    }
    float inv = 1.f / ((rs == 0.f) ? 1e-12f : rs);
    float cin = 1.f / fmaxf(cnt, 1.f);
    size_t ob = (size_t)w * 32 + l;
    ((float4*)out0)[ob] = make_float4(eluf(num.x * inv), eluf(num.y * inv),
                                      eluf(num.z * inv), eluf(num.w * inv));
    ((float4*)out2)[ob] = make_float4(eluf(num.x), eluf(num.y), eluf(num.z), eluf(num.w));
    ((float4*)out3)[ob] = make_float4(eluf(unif.x * cin), eluf(unif.y * cin),
                                      eluf(unif.z * cin), eluf(unif.w * cin));
}

// ---------------- launch ----------------
extern "C" void kernel_launch(void* const* d_in, const int* in_sizes, int n_in,
                              void* d_out, int out_size) {
    const float* ent  = (const float*)d_in[0];
    const float* rel  = (const float*)d_in[1];
    const float* eemb = (const float*)d_in[2];
    const float* ah   = (const float*)d_in[3];
    const float* a2h  = (const float*)d_in[4];
    const float* W    = (const float*)d_in[5];
    const float* ao   = (const float*)d_in[6];
    const float* a2o  = (const float*)d_in[7];
    const int* el     = (const int*)d_in[8];
    const int* et     = (const int*)d_in[9];
    const int* elnh   = (const int*)d_in[10];
    const int* etnh   = (const int*)d_in[11];
    float* out = (float*)d_out;
    float* out_rel = out + (size_t)N_ * 128;                 // part 1
    float* out0 = out;                                       // elu(h)
    float* out2 = out + (size_t)N_ * 128 + NREL_ * 128;      // elu(h_num)
    float* out3 = out + (size_t)2 * N_ * 128 + NREL_ * 128;  // elu(h_unif)

    k_prep<<<321, 256>>>(ah, ao, a2h);
    k_outrel<<<250, 256>>>(rel, W, out_rel);
    k_relproj2<<<250, 256>>>(out_rel, ao);
    k_rels2<<<2, 256>>>(a2o);

    k_zero<<<196, 256>>>();
    k_hist<<<1760, 512>>>(el, elnh);
    k_scan<<<1, 1024>>>();
    k_scatter<<<1760, 512>>>(el, elnh);

    dim3 gpm(4, 391);
    k_gemm_pm1<<<gpm, 128>>>(ent);
    k_s1<<<6250, 256>>>(a2h);
    k_edge1<<<6250, 256>>>(el, elnh, etnh, eemb, rel);
    dim3 ghp(1, 391);
    k_gemm_hp0<<<ghp, 128>>>();
    k_gemm_hp1<<<ghp, 128>>>();
    k_fin1<<<25000, 256>>>();

    k_gemm_pm2<<<gpm, 128>>>();
    k_s2<<<6250, 256>>>(a2o);
    k_edge2<<<6250, 256>>>(el, elnh, et, etnh, out0, out2, out3);
}

// round 17
// speedup vs baseline: 1.0006x; 1.0006x over previous
#include <cuda_runtime.h>
#include <cstdint>
#include <cstddef>

#define N_     50000
#define E_     800000
#define EN_    100000
#define ET_    900000
#define NREL_  500

// ---------------- scratch (__device__ globals; no cudaMalloc allowed) ----------------
__device__ int   g_cnt[N_];
__device__ int   g_cur[N_];
__device__ int   g_start[N_ + 1];
__device__ int   g_csr[ET_];

__device__ float g_B1[256 * 128];          // layer-1 packed src|dst proj rows
__device__ float g_B2[256 * 128];          // layer-2 packed src|dst proj rows
__device__ float g_arel[2 * 64 * 128];     // per-head a_rel [h][j][k]
__device__ float g_u1[2 * 128];            // u_h = a_rel_h^T a2_h

__device__ float g_pm1[(size_t)N_ * 256];  // [n][src h0|src h1|dst h0|dst h1]
__device__ float g_s1[N_ * 4];             // [n][ssrc0 ssrc1 sdst0 sdst1]
__device__ float g_agg[(size_t)N_ * 256];  // [n][h0 v-agg 128 | h1 v-agg 128]
__device__ float g_aggdst[(size_t)N_ * 128];
__device__ float g_rs1[N_ * 2];
__device__ float g_hp[(size_t)N_ * 128];
__device__ float g_x2[(size_t)N_ * 128];
__device__ float g_pm2[(size_t)N_ * 256];  // [n][src 128 | dst 128]
__device__ float g_s2[N_ * 2];
__device__ float g_relproj2[NREL_ * 128];
__device__ float g_rels2[NREL_];

// ---------------- helpers ----------------
__device__ __forceinline__ float eluf(float x) { return x > 0.f ? x : expm1f(x); }
__device__ __forceinline__ float attw(float p) {
    float lk = p > 0.f ? p : 0.2f * p;     // leaky_relu(p, 0.2)
    return __expf(-lk);
}

// ---------------- small precompute ----------------
__global__ void k_prep(const float* __restrict__ ah, const float* __restrict__ ao,
                       const float* __restrict__ a2h) {
    int idx = blockIdx.x * blockDim.x + threadIdx.x;
    if (idx < 32768) {                       // B1
        int r = idx >> 7, k = idx & 127;
        int rr = (r < 128) ? r : r - 128;
        int h = rr >> 6, j = rr & 63;
        int kk = (r < 128) ? k : 128 + k;
        g_B1[idx] = ah[(h * 64 + j) * 384 + kk];
    } else if (idx < 65536) {                // B2
        int e = idx - 32768;
        int r = e >> 7, k = e & 127;
        g_B2[e] = (r < 128) ? ao[r * 384 + k] : ao[(r - 128) * 384 + 128 + k];
    } else if (idx < 81920) {                // arel
        int e = idx - 65536;
        int h = e >> 13, j = (e >> 7) & 63, k = e & 127;
        g_arel[e] = ah[(h * 64 + j) * 384 + 256 + k];
    } else if (idx < 82176) {                // u1
        int e = idx - 81920;
        int h = e >> 7, k = e & 127;
        float s = 0.f;
        for (int j = 0; j < 64; ++j)
            s = fmaf(ah[(h * 64 + j) * 384 + 256 + k], a2h[h * 64 + j], s);
        g_u1[e] = s;
    }
}

__global__ void k_outrel(const float* __restrict__ rel, const float* __restrict__ W,
                         float* __restrict__ out_rel) {
    int idx = blockIdx.x * blockDim.x + threadIdx.x;
    if (idx >= NREL_ * 128) return;
    int r = idx >> 7, c = idx & 127;
    float s = 0.f;
    #pragma unroll 8
    for (int k = 0; k < 128; ++k) s = fmaf(rel[r * 128 + k], W[k * 128 + c], s);
    out_rel[idx] = s;
}

__global__ void k_relproj2(const float* __restrict__ out_rel, const float* __restrict__ ao) {
    int idx = blockIdx.x * blockDim.x + threadIdx.x;
    if (idx >= NREL_ * 128) return;
    int r = idx >> 7, j = idx & 127;
    float s = 0.f;
    #pragma unroll 8
    for (int k = 0; k < 128; ++k) s = fmaf(out_rel[r * 128 + k], ao[j * 384 + 256 + k], s);
    g_relproj2[idx] = s;
}

__global__ void k_rels2(const float* __restrict__ a2o) {
    int r = blockIdx.x * blockDim.x + threadIdx.x;
    if (r >= NREL_) return;
    float s = 0.f;
    #pragma unroll 8
    for (int j = 0; j < 128; ++j) s = fmaf(g_relproj2[r * 128 + j], a2o[j], s);
    g_rels2[r] = s;
}

// ---------------- CSR build (shared by both layers; same e0) ----------------
__global__ void k_zero() {
    int i = blockIdx.x * blockDim.x + threadIdx.x;
    if (i < N_) { g_cnt[i] = 0; g_cur[i] = 0; }
}

__global__ void k_hist(const int* __restrict__ el, const int* __restrict__ elnh) {
    for (int i = blockIdx.x * blockDim.x + threadIdx.x; i < ET_; i += gridDim.x * blockDim.x) {
        int n = (i < E_) ? el[i] : elnh[i - E_];
        atomicAdd(&g_cnt[n], 1);
    }
}

__global__ void k_scan() {
    __shared__ int sm[1024];
    const int t = threadIdx.x;
    const int C = 49;                       // 1024*49 >= 50000
    int base = t * C;
    int s = 0;
    for (int i = 0; i < C; ++i) { int idx = base + i; if (idx < N_) s += g_cnt[idx]; }
    sm[t] = s;
    __syncthreads();
    for (int off = 1; off < 1024; off <<= 1) {
        int v = (t >= off) ? sm[t - off] : 0;
        __syncthreads();
        sm[t] += v;
        __syncthreads();
    }
    int run = sm[t] - s;                    // exclusive prefix
    for (int i = 0; i < C; ++i) {
        int idx = base + i;
        if (idx < N_) { g_start[idx] = run; run += g_cnt[idx]; }
    }
    if (t == 1023) g_start[N_] = sm[1023];
}

__global__ void k_scatter(const int* __restrict__ el, const int* __restrict__ elnh) {
    for (int i = blockIdx.x * blockDim.x + threadIdx.x; i < ET_; i += gridDim.x * blockDim.x) {
        int n = (i < E_) ? el[i] : elnh[i - E_];
        int pos = g_start[n] + atomicAdd(&g_cur[n], 1);
        g_csr[pos] = i;
    }
}

// ---------------- SGEMM: C[M,*] = A[M,128] @ B[*,128]^T, 128x64 tile ----------------
__device__ __forceinline__ void sgemm_body(int M, const float* __restrict__ A, int lda,
                                           const float* __restrict__ B,
                                           float* __restrict__ C, int ldc) {
    __shared__ float As[32][129];
    __shared__ float Bs[32][65];
    const int tid = threadIdx.x;
    const int rb = blockIdx.y * 128;
    const int nb = blockIdx.x * 64;
    const int m0 = (tid >> 3) * 8;
    const int n0 = (tid & 7) * 8;
    float acc[8][8] = {};
    for (int kc = 0; kc < 128; kc += 32) {
        #pragma unroll
        for (int it = 0; it < 8; ++it) {
            int fidx = tid + it * 128;
            int r = fidx >> 3, q = fidx & 7;
            float4 v = make_float4(0.f, 0.f, 0.f, 0.f);
            int row = rb + r;
            if (row < M) v = *reinterpret_cast<const float4*>(A + (size_t)row * lda + kc + q * 4);
            As[q * 4 + 0][r] = v.x; As[q * 4 + 1][r] = v.y;
            As[q * 4 + 2][r] = v.z; As[q * 4 + 3][r] = v.w;
        }
        #pragma unroll
        for (int it = 0; it < 4; ++it) {
            int fidx = tid + it * 128;
            int r = fidx >> 3, q = fidx & 7;
            float4 v = *reinterpret_cast<const float4*>(B + (size_t)(nb + r) * 128 + kc + q * 4);
            Bs[q * 4 + 0][r] = v.x; Bs[q * 4 + 1][r] = v.y;
            Bs[q * 4 + 2][r] = v.z; Bs[q * 4 + 3][r] = v.w;
        }
        __syncthreads();
        #pragma unroll
        for (int k = 0; k < 32; ++k) {
            float a[8], b[8];
            #pragma unroll
            for (int i = 0; i < 8; ++i) a[i] = As[k][m0 + i];
            #pragma unroll
            for (int j = 0; j < 8; ++j) b[j] = Bs[k][n0 + j];
            #pragma unroll
            for (int i = 0; i < 8; ++i)
                #pragma unroll
                for (int j = 0; j < 8; ++j)
                    acc[i][j] = fmaf(a[i], b[j], acc[i][j]);
        }
        __syncthreads();
    }
    #pragma unroll
    for (int i = 0; i < 8; ++i) {
        int row = rb + m0 + i;
        if (row < M) {
            *reinterpret_cast<float4*>(C + (size_t)row * ldc + nb + n0) =
                make_float4(acc[i][0], acc[i][1], acc[i][2], acc[i][3]);
            *reinterpret_cast<float4*>(C + (size_t)row * ldc + nb + n0 + 4) =
                make_float4(acc[i][4], acc[i][5], acc[i][6], acc[i][7]);
        }
    }
}

__global__ void __launch_bounds__(128) k_gemm_pm1(const float* __restrict__ A) {
    sgemm_body(N_, A, 128, g_B1, g_pm1, 256);
}
__global__ void __launch_bounds__(128) k_gemm_pm2() {
    sgemm_body(N_, g_x2, 128, g_B2, g_pm2, 256);
}
__global__ void __launch_bounds__(128) k_gemm_hp0() {
    sgemm_body(N_, g_agg, 256, g_arel, g_hp, 128);
}
__global__ void __launch_bounds__(128) k_gemm_hp1() {
    sgemm_body(N_, g_agg + 128, 256, g_arel + 64 * 128, g_hp + 64, 128);
}

// ---------------- per-node logit scalars ----------------
__global__ void k_s1(const float* __restrict__ a2h) {
    int w = (blockIdx.x * blockDim.x + threadIdx.x) >> 5;
    int l = threadIdx.x & 31;
    if (w >= N_) return;
    const float* row = g_pm1 + (size_t)w * 256;
    float ps[4] = {0.f, 0.f, 0.f, 0.f};
    #pragma unroll
    for (int i = 0; i < 8; ++i) {
        int idx = l + 32 * i;
        int s = i >> 1;                 // 0:src h0, 1:src h1, 2:dst h0, 3:dst h1
        int head = s & 1;
        ps[s] = fmaf(row[idx], a2h[head * 64 + (idx & 63)], ps[s]);
    }
    #pragma unroll
    for (int off = 16; off; off >>= 1) {
        #pragma unroll
        for (int s = 0; s < 4; ++s) ps[s] += __shfl_xor_sync(0xffffffffu, ps[s], off);
    }
    if (l == 0) {
        g_s1[w * 4 + 0] = ps[0]; g_s1[w * 4 + 1] = ps[1];
        g_s1[w * 4 + 2] = ps[2]; g_s1[w * 4 + 3] = ps[3];
    }
}

__global__ void k_s2(const float* __restrict__ a2o) {
    int w = (blockIdx.x * blockDim.x + threadIdx.x) >> 5;
    int l = threadIdx.x & 31;
    if (w >= N_) return;
    const float4* pm4 = (const float4*)g_pm2;
    const float4* a4 = (const float4*)a2o;
    float4 av = a4[l];
    float4 sv = pm4[(size_t)w * 64 + l];
    float4 dv = pm4[(size_t)w * 64 + 32 + l];
    float p0 = sv.x * av.x + sv.y * av.y + sv.z * av.z + sv.w * av.w;
    float p1 = dv.x * av.x + dv.y * av.y + dv.z * av.z + dv.w * av.w;
    #pragma unroll
    for (int off = 16; off; off >>= 1) {
        p0 += __shfl_xor_sync(0xffffffffu, p0, off);
        p1 += __shfl_xor_sync(0xffffffffu, p1, off);
    }
    if (l == 0) { g_s2[2 * w] = p0; g_s2[2 * w + 1] = p1; }
}

// ---------------- layer-1 edge pass (warp per node) ----------------
__global__ void k_edge1(const int* __restrict__ el, const int* __restrict__ elnh,
                        const int* __restrict__ etnh,
                        const float* __restrict__ eemb, const float* __restrict__ rel) {
    int w = (blockIdx.x * blockDim.x + threadIdx.x) >> 5;
    int l = threadIdx.x & 31;
    if (w >= N_) return;
    const float4* eemb4 = (const float4*)eemb;
    const float4* rel4 = (const float4*)rel;
    const float4* u4 = (const float4*)g_u1;
    const float4* pm4 = (const float4*)g_pm1;
    float4 u0 = u4[l], u1 = u4[32 + l];
    float ssrc0 = g_s1[w * 4 + 0], ssrc1 = g_s1[w * 4 + 1];
    float4 a0 = make_float4(0.f, 0.f, 0.f, 0.f);
    float4 a1 = make_float4(0.f, 0.f, 0.f, 0.f);
    float4 ad = make_float4(0.f, 0.f, 0.f, 0.f);
    float rs0 = 0.f, rs1 = 0.f;
    int s = g_start[w], e = g_start[w + 1];
    for (int p = s; p < e; ++p) {
        int eid = g_csr[p];
        int dst; float4 v;
        if (eid < E_) {
            dst = el[E_ + eid];
            v = eemb4[(size_t)eid * 32 + l];
        } else {
            int q = eid - E_;
            dst = elnh[EN_ + q];
            int t0 = etnh[2 * q], t1 = etnh[2 * q + 1];
            float4 x = rel4[t0 * 32 + l], y = rel4[t1 * 32 + l];
            v = make_float4(x.x + y.x, x.y + y.y, x.z + y.z, x.w + y.w);
        }
        float d0 = v.x * u0.x + v.y * u0.y + v.z * u0.z + v.w * u0.w;
        float d1 = v.x * u1.x + v.y * u1.y + v.z * u1.z + v.w * u1.w;
        #pragma unroll
        for (int off = 16; off; off >>= 1) {
            d0 += __shfl_xor_sync(0xffffffffu, d0, off);
            d1 += __shfl_xor_sync(0xffffffffu, d1, off);
        }
        float w0 = attw(ssrc0 + g_s1[dst * 4 + 2] + d0);
        float w1 = attw(ssrc1 + g_s1[dst * 4 + 3] + d1);
        rs0 += w0; rs1 += w1;
        a0.x = fmaf(w0, v.x, a0.x); a0.y = fmaf(w0, v.y, a0.y);
        a0.z = fmaf(w0, v.z, a0.z); a0.w = fmaf(w0, v.w, a0.w);
        a1.x = fmaf(w1, v.x, a1.x); a1.y = fmaf(w1, v.y, a1.y);
        a1.z = fmaf(w1, v.z, a1.z); a1.w = fmaf(w1, v.w, a1.w);
        float4 pd = pm4[(size_t)dst * 64 + 32 + l];   // dst-proj, both heads packed
        float ww = (l < 16) ? w0 : w1;
        ad.x = fmaf(ww, pd.x, ad.x); ad.y = fmaf(ww, pd.y, ad.y);
        ad.z = fmaf(ww, pd.z, ad.z); ad.w = fmaf(ww, pd.w, ad.w);
    }
    float4* agg4 = (float4*)g_agg;
    agg4[(size_t)w * 64 + l] = a0;
    agg4[(size_t)w * 64 + 32 + l] = a1;
    ((float4*)g_aggdst)[(size_t)w * 32 + l] = ad;
    if (l == 0) { g_rs1[2 * w] = rs0; g_rs1[2 * w + 1] = rs1; }
}

// ---------------- layer-1 finalize: x2 = elu(h) ----------------
__global__ void k_fin1() {
    int idx = blockIdx.x * blockDim.x + threadIdx.x;
    if (idx >= N_ * 128) return;
    int n = idx >> 7, j = idx & 127, h = j >> 6;
    float rs = g_rs1[2 * n + h];
    float num = fmaf(rs, g_pm1[(size_t)n * 256 + j],
                     g_aggdst[(size_t)n * 128 + j] + g_hp[(size_t)n * 128 + j]);
    float rsadj = (rs == 0.f) ? 1e-12f : rs;
    g_x2[(size_t)n * 128 + j] = eluf(num / rsadj);
}

// ---------------- layer-2 edge pass + fused finalize ----------------
__global__ void k_edge2(const int* __restrict__ el, const int* __restrict__ elnh,
                        const int* __restrict__ et, const int* __restrict__ etnh,
                        float* __restrict__ out0, float* __restrict__ out2,
                        float* __restrict__ out3) {
    int w = (blockIdx.x * blockDim.x + threadIdx.x) >> 5;
    int l = threadIdx.x & 31;
    if (w >= N_) return;
    const float4* pm4 = (const float4*)g_pm2;
    const float4* rp4 = (const float4*)g_relproj2;
    float4 ps = pm4[(size_t)w * 64 + l];
    float ssrc = g_s2[2 * w];
    float4 num = make_float4(0.f, 0.f, 0.f, 0.f);
    float4 unif = make_float4(0.f, 0.f, 0.f, 0.f);
    float rs = 0.f, cnt = 0.f;
    int s = g_start[w], e = g_start[w + 1];
    for (int p = s; p < e; ++p) {
        int eid = g_csr[p];
        int dst; float4 rp; float rels;
        if (eid < E_) {
            dst = el[E_ + eid];
            int r = et[eid];
            rp = rp4[r * 32 + l];
            rels = g_rels2[r];
        } else {
            int q = eid - E_;
            dst = elnh[EN_ + q];
            int t0 = etnh[2 * q], t1 = etnh[2 * q + 1];
            float4 x = rp4[t0 * 32 + l], y = rp4[t1 * 32 + l];
            rp = make_float4(x.x + y.x, x.y + y.y, x.z + y.z, x.w + y.w);
            rels = g_rels2[t0] + g_rels2[t1];
        }
        float4 pd = pm4[(size_t)dst * 64 + 32 + l];
        float wgt = attw(ssrc + g_s2[2 * dst + 1] + rels);
        float4 m = make_float4(ps.x + pd.x + rp.x, ps.y + pd.y + rp.y,
                               ps.z + pd.z + rp.z, ps.w + pd.w + rp.w);
        rs += wgt; cnt += 1.f;
        num.x = fmaf(wgt, m.x, num.x); num.y = fmaf(wgt, m.y, num.y);
        num.z = fmaf(wgt, m.z, num.z); num.w = fmaf(wgt, m.w, num.w);
        unif.x += m.x; unif.y += m.y; unif.z += m.z; unif.w += m.w;
    }
    float inv = 1.f / ((rs == 0.f) ? 1e-12f : rs);
    float cin = 1.f / fmaxf(cnt, 1.f);
    size_t ob = (size_t)w * 32 + l;
    ((float4*)out0)[ob] = make_float4(eluf(num.x * inv), eluf(num.y * inv),
                                      eluf(num.z * inv), eluf(num.w * inv));
    ((float4*)out2)[ob] = make_float4(eluf(num.x), eluf(num.y), eluf(num.z), eluf(num.w));
    ((float4*)out3)[ob] = make_float4(eluf(unif.x * cin), eluf(unif.y * cin),
                                      eluf(unif.z * cin), eluf(unif.w * cin));
}

// ---------------- launch ----------------
extern "C" void kernel_launch(void* const* d_in, const int* in_sizes, int n_in,
                              void* d_out, int out_size) {
    const float* ent  = (const float*)d_in[0];
    const float* rel  = (const float*)d_in[1];
    const float* eemb = (const float*)d_in[2];
    const float* ah   = (const float*)d_in[3];
    const float* a2h  = (const float*)d_in[4];
    const float* W    = (const float*)d_in[5];
    const float* ao   = (const float*)d_in[6];
    const float* a2o  = (const float*)d_in[7];
    const int* el     = (const int*)d_in[8];
    const int* et     = (const int*)d_in[9];
    const int* elnh   = (const int*)d_in[10];
    const int* etnh   = (const int*)d_in[11];
    float* out = (float*)d_out;
    float* out_rel = out + (size_t)N_ * 128;                 // part 1
    float* out0 = out;                                       // elu(h)
    float* out2 = out + (size_t)N_ * 128 + NREL_ * 128;      // elu(h_num)
    float* out3 = out + (size_t)2 * N_ * 128 + NREL_ * 128;  // elu(h_unif)

    k_prep<<<321, 256>>>(ah, ao, a2h);
    k_outrel<<<250, 256>>>(rel, W, out_rel);
    k_relproj2<<<250, 256>>>(out_rel, ao);
    k_rels2<<<2, 256>>>(a2o);

    k_zero<<<196, 256>>>();
    k_hist<<<1760, 512>>>(el, elnh);
    k_scan<<<1, 1024>>>();
    k_scatter<<<1760, 512>>>(el, elnh);

    dim3 gpm(4, 391);
    k_gemm_pm1<<<gpm, 128>>>(ent);
    k_s1<<<6250, 256>>>(a2h);
    k_edge1<<<6250, 256>>>(el, elnh, etnh, eemb, rel);
    dim3 ghp(1, 391);
    k_gemm_hp0<<<ghp, 128>>>();
    k_gemm_hp1<<<ghp, 128>>>();
    k_fin1<<<25000, 256>>>();

    k_gemm_pm2<<<gpm, 128>>>();
    k_s2<<<6250, 256>>>(a2o);
    k_edge2<<<6250, 256>>>(el, elnh, et, etnh, out0, out2, out3);
}